// round 5
// baseline (speedup 1.0000x reference)
#include <cuda_runtime.h>
#include <math.h>

#define BATCH 8
#define CI    256
#define CO    256
#define H     64
#define W     64
#define HW    4096
#define M_TOT 32768          // BATCH*HW
#define KDIM  2304           // CI*9
#define EPSV  1e-5f

// ---------------- scratch (__device__ globals: allocation-free rule) -------
__device__ float  g_val[KDIM * M_TOT];       // 302 MB: val[k=(ci*9+kk)][m=b*HW+pix]
__device__ float4 g_par[BATCH * 9 * HW];     // (py, px, mask, -) per (b,kk,pixel)
__device__ float  g_wT[KDIM * CO];           // wT[k][co] = w[co][k] * bn_scale[co]

// ================= Phase A: offset conv -> bilinear params =================
// om[b,oc,h,w] = b_off[oc] + sum_{ci,ky,kx} x[b,ci,h+ky-1,w+kx-1]*w_off[oc,ci,ky,kx]
// dy=om[0..8], dx=om[9..17], mask=sigmoid(om[18..26])
__global__ __launch_bounds__(256) void offset_kernel(
    const float* __restrict__ x, const float* __restrict__ w_off,
    const float* __restrict__ b_off)
{
    __shared__ float  xs[18 * 18];
    __shared__ float4 ws4[81];                 // [27][12] padded weights
    float* ws = (float*)ws4;

    int b    = blockIdx.y;
    int tile = blockIdx.x;                     // 16 tiles of 16x16
    int h0 = (tile >> 2) << 4;
    int w0 = (tile & 3) << 4;
    int tid = threadIdx.x;
    int ty = tid >> 4, tx = tid & 15;
    int h = h0 + ty, ww = w0 + tx;

    float acc[27];
#pragma unroll
    for (int i = 0; i < 27; i++) acc[i] = 0.f;

    const float* xb = x + b * (CI * HW);
    for (int ci = 0; ci < CI; ci++) {
        __syncthreads();
        // stage 18x18 x-tile (zero padded)
        for (int i = tid; i < 324; i += 256) {
            int r = i / 18, c = i - r * 18;
            int gy = h0 + r - 1, gx = w0 + c - 1;
            float v = 0.f;
            if (gy >= 0 && gy < H && gx >= 0 && gx < W)
                v = xb[ci * HW + gy * W + gx];
            xs[i] = v;
        }
        // stage 27x9 weights padded to 27x12 for float4 reads
        // (strided loop: 324 entries > 256 threads — the tid<324 guard alone
        //  left entries 256..323, i.e. mask-channel weights oc=21..26, unset)
        for (int i = tid; i < 324; i += 256) {
            int oc = i / 12, j = i - oc * 12;
            ws[i] = (j < 9) ? w_off[oc * KDIM + ci * 9 + j] : 0.f;
        }
        __syncthreads();

        float xv[9];
#pragma unroll
        for (int ky = 0; ky < 3; ky++)
#pragma unroll
            for (int kx = 0; kx < 3; kx++)
                xv[ky * 3 + kx] = xs[(ty + ky) * 18 + tx + kx];

        const float4* w4 = (const float4*)ws;
#pragma unroll
        for (int oc = 0; oc < 27; oc++) {
            float4 a0 = w4[oc * 3 + 0], a1 = w4[oc * 3 + 1], a2 = w4[oc * 3 + 2];
            acc[oc] += xv[0] * a0.x + xv[1] * a0.y + xv[2] * a0.z + xv[3] * a0.w
                     + xv[4] * a1.x + xv[5] * a1.y + xv[6] * a1.z + xv[7] * a1.w
                     + xv[8] * a2.x;
        }
    }

    int pix = h * W + ww;
#pragma unroll
    for (int kk = 0; kk < 9; kk++) {
        float dy = acc[kk]      + b_off[kk];
        float dx = acc[9 + kk]  + b_off[9 + kk];
        float z  = acc[18 + kk] + b_off[18 + kk];
        float msk = 1.f / (1.f + __expf(-z));
        float py = (float)(h  + (kk / 3) - 1) + dy;
        float px = (float)(ww + (kk % 3) - 1) + dx;
        g_par[(b * 9 + kk) * HW + pix] = make_float4(py, px, msk, 0.f);
    }
}

// ============ Phase W: weight transpose + BN scale fold =====================
__global__ void wt_kernel(const float* __restrict__ w,
                          const float* __restrict__ gamma,
                          const float* __restrict__ var)
{
    int k  = blockIdx.x;     // 0..KDIM-1
    int co = threadIdx.x;    // 0..255
    float alpha = gamma[co] * rsqrtf(var[co] + EPSV);
    g_wT[k * CO + co] = w[co * KDIM + k] * alpha;
}

// ============ Phase B: bilinear sampling -> g_val (GEMM layout) =============
__global__ __launch_bounds__(256) void sample_kernel(const float* __restrict__ x)
{
    int bk    = blockIdx.x >> 4;            // b*9+kk
    int chunk = blockIdx.x & 15;
    int pix   = chunk * 256 + threadIdx.x;
    int b  = bk / 9;
    int kk = bk - b * 9;

    float4 par = g_par[bk * HW + pix];
    float py = par.x, px = par.y, msk = par.z;
    float y0f = floorf(py), x0f = floorf(px);
    float wy = py - y0f, wx = px - x0f;
    int y0 = (int)y0f, x0 = (int)x0f;

    bool vy0 = (y0 >= 0)  && (y0 < H);
    bool vy1 = (y0 >= -1) && (y0 < H - 1);
    bool vx0 = (x0 >= 0)  && (x0 < W);
    bool vx1 = (x0 >= -1) && (x0 < W - 1);

    float w00 = (1.f - wy) * (1.f - wx) * msk * ((vy0 && vx0) ? 1.f : 0.f);
    float w01 = (1.f - wy) * wx         * msk * ((vy0 && vx1) ? 1.f : 0.f);
    float w10 = wy * (1.f - wx)         * msk * ((vy1 && vx0) ? 1.f : 0.f);
    float w11 = wy * wx                 * msk * ((vy1 && vx1) ? 1.f : 0.f);

    int y0c = min(max(y0, 0), H - 1),  y1c = min(max(y0 + 1, 0), H - 1);
    int x0c = min(max(x0, 0), W - 1),  x1c = min(max(x0 + 1, 0), W - 1);
    int o00 = y0c * W + x0c, o01 = y0c * W + x1c;
    int o10 = y1c * W + x0c, o11 = y1c * W + x1c;

    const float* xb = x + b * (CI * HW);
    int outBase = kk * M_TOT + b * HW + pix;

#pragma unroll 4
    for (int ci = 0; ci < CI; ci++) {
        const float* xp = xb + ci * HW;
        float v = w00 * xp[o00] + w01 * xp[o01] + w10 * xp[o10] + w11 * xp[o11];
        g_val[ci * 9 * M_TOT + outBase] = v;
    }
}

// ============ Phase C: f32x2 GEMM + bias/BN-shift/ReLU ======================
__device__ __forceinline__ unsigned long long ffma2(
    unsigned long long a, unsigned long long b, unsigned long long c)
{
    unsigned long long d;
    asm("fma.rn.f32x2 %0, %1, %2, %3;" : "=l"(d) : "l"(a), "l"(b), "l"(c));
    return d;
}
__device__ __forceinline__ unsigned long long bcast2(float v)
{
    unsigned long long d;
    asm("mov.b64 %0, {%1, %1};" : "=l"(d) : "r"(__float_as_uint(v)));
    return d;
}

#define MT 128
#define NT 128
#define KC 16

__global__ __launch_bounds__(256, 2) void gemm_kernel(
    const float* __restrict__ bias,  const float* __restrict__ gamma,
    const float* __restrict__ beta,  const float* __restrict__ mean,
    const float* __restrict__ var,   float* __restrict__ out)
{
    __shared__ float As[KC][MT];
    __shared__ float Bs[KC][NT];

    int m0 = blockIdx.x * MT;
    int n0 = blockIdx.y * NT;
    int tid = threadIdx.x;
    int tx = tid & 15;     // co micro-group
    int ty = tid >> 4;     // pixel micro-group

    unsigned long long acc[8][4];
#pragma unroll
    for (int j = 0; j < 8; j++)
#pragma unroll
        for (int p = 0; p < 4; p++) acc[j][p] = 0ULL;

    for (int k0 = 0; k0 < KDIM; k0 += KC) {
#pragma unroll
        for (int t = tid; t < 512; t += 256) {
            int r = t >> 5, c4 = (t & 31) << 2;
            *(float4*)&As[r][c4] = *(const float4*)&g_val[(k0 + r) * M_TOT + m0 + c4];
            *(float4*)&Bs[r][c4] = *(const float4*)&g_wT[(k0 + r) * CO + n0 + c4];
        }
        __syncthreads();
#pragma unroll
        for (int kk = 0; kk < KC; kk++) {
            ulonglong2 a01 = *(const ulonglong2*)&As[kk][ty * 8];
            ulonglong2 a23 = *(const ulonglong2*)&As[kk][ty * 8 + 4];
            unsigned long long ap[4] = { a01.x, a01.y, a23.x, a23.y };
            float4 b0 = *(const float4*)&Bs[kk][tx * 8];
            float4 b1 = *(const float4*)&Bs[kk][tx * 8 + 4];
            unsigned long long bp[8];
            bp[0] = bcast2(b0.x); bp[1] = bcast2(b0.y);
            bp[2] = bcast2(b0.z); bp[3] = bcast2(b0.w);
            bp[4] = bcast2(b1.x); bp[5] = bcast2(b1.y);
            bp[6] = bcast2(b1.z); bp[7] = bcast2(b1.w);
#pragma unroll
            for (int j = 0; j < 8; j++)
#pragma unroll
                for (int p = 0; p < 4; p++)
                    acc[j][p] = ffma2(ap[p], bp[j], acc[j][p]);
        }
        __syncthreads();
    }

    // epilogue: + (b - mean)*alpha + beta, ReLU  (alpha already folded into wT)
    int m_base = m0 + ty * 8;
    int b_idx  = m_base >> 12;        // batch
    int hw     = m_base & 4095;
#pragma unroll
    for (int j = 0; j < 8; j++) {
        int co = n0 + tx * 8 + j;
        float alpha = gamma[co] * rsqrtf(var[co] + EPSV);
        float delta = fmaf(bias[co] - mean[co], alpha, beta[co]);
        float* op = out + b_idx * (CO * HW) + co * HW + hw;
#pragma unroll
        for (int p = 0; p < 4; p++) {
            unsigned long long v = acc[j][p];
            float lo = __uint_as_float((unsigned int)(v & 0xffffffffu));
            float hi = __uint_as_float((unsigned int)(v >> 32));
            lo = fmaxf(lo + delta, 0.f);
            hi = fmaxf(hi + delta, 0.f);
            op[p * 2]     = lo;
            op[p * 2 + 1] = hi;
        }
    }
}

// ===========================================================================
extern "C" void kernel_launch(void* const* d_in, const int* in_sizes, int n_in,
                              void* d_out, int out_size)
{
    const float* x     = (const float*)d_in[0];
    const float* w_off = (const float*)d_in[1];
    const float* b_off = (const float*)d_in[2];
    const float* w     = (const float*)d_in[3];
    const float* bias  = (const float*)d_in[4];
    const float* gamma = (const float*)d_in[5];
    const float* beta  = (const float*)d_in[6];
    const float* mean  = (const float*)d_in[7];
    const float* var   = (const float*)d_in[8];
    float* out = (float*)d_out;

    offset_kernel<<<dim3(16, 8), 256>>>(x, w_off, b_off);
    wt_kernel<<<KDIM, 256>>>(w, gamma, var);
    sample_kernel<<<1152, 256>>>(x);
    gemm_kernel<<<dim3(256, 2), 256>>>(bias, gamma, beta, mean, var, out);
}

// round 8
// speedup vs baseline: 1.3068x; 1.3068x over previous
#include <cuda_runtime.h>
#include <math.h>
#include <stdint.h>

#define BATCH 8
#define CI    256
#define CO    256
#define H     64
#define W     64
#define HW    4096
#define M_TOT 32768          // BATCH*HW
#define KDIM  2304           // CI*9
#define EPSV  1e-5f

// ---------------- scratch (__device__ globals: allocation-free rule) -------
__device__ float  g_valA[(size_t)M_TOT * KDIM]; // [m][k] tf32-rounded samples (302 MB)
__device__ float4 g_par[BATCH * 9 * HW];        // (py, px, mask, -) per (b,kk,pixel)
__device__ float  g_wB[CO * KDIM];              // [co][k-permuted], w*bn_scale, tf32-rounded

// ===================== small helpers ========================================
__device__ __forceinline__ uint32_t smem_u32(const void* p) {
    uint32_t a;
    asm("{ .reg .u64 t; cvta.to.shared.u64 t, %1; cvt.u32.u64 %0, t; }" : "=r"(a) : "l"(p));
    return a;
}
__device__ __forceinline__ float tf32_rna(float v) {
    uint32_t u;
    asm("cvt.rna.tf32.f32 %0, %1;" : "=r"(u) : "f"(v));
    return __uint_as_float(u);
}
__device__ __forceinline__ void cp_async16(uint32_t dst, const void* src) {
    asm volatile("cp.async.cg.shared.global [%0], [%1], 16;" :: "r"(dst), "l"(src) : "memory");
}
#define CP_COMMIT() asm volatile("cp.async.commit_group;" ::: "memory")
#define CP_WAIT0()  asm volatile("cp.async.wait_group 0;" ::: "memory")

__device__ __forceinline__ void mma_tf32(float& c0, float& c1, float& c2, float& c3,
                                         uint32_t a0, uint32_t a1, uint32_t a2, uint32_t a3,
                                         uint32_t b0, uint32_t b1) {
    asm volatile(
        "mma.sync.aligned.m16n8k8.row.col.f32.tf32.tf32.f32 "
        "{%0,%1,%2,%3}, {%4,%5,%6,%7}, {%8,%9}, {%0,%1,%2,%3};"
        : "+f"(c0), "+f"(c1), "+f"(c2), "+f"(c3)
        : "r"(a0), "r"(a1), "r"(a2), "r"(a3), "r"(b0), "r"(b1));
}

// ================= Phase A: offset conv -> bilinear params =================
__global__ __launch_bounds__(256) void offset_kernel(
    const float* __restrict__ x, const float* __restrict__ w_off,
    const float* __restrict__ b_off)
{
    __shared__ float  xs[18 * 18];
    __shared__ float4 ws4[81];                 // [27][12] padded weights
    float* ws = (float*)ws4;

    int b    = blockIdx.y;
    int tile = blockIdx.x;                     // 16 tiles of 16x16
    int h0 = (tile >> 2) << 4;
    int w0 = (tile & 3) << 4;
    int tid = threadIdx.x;
    int ty = tid >> 4, tx = tid & 15;
    int h = h0 + ty, ww = w0 + tx;

    float acc[27];
#pragma unroll
    for (int i = 0; i < 27; i++) acc[i] = 0.f;

    const float* xb = x + b * (CI * HW);
    for (int ci = 0; ci < CI; ci++) {
        __syncthreads();
        for (int i = tid; i < 324; i += 256) {
            int r = i / 18, c = i - r * 18;
            int gy = h0 + r - 1, gx = w0 + c - 1;
            float v = 0.f;
            if (gy >= 0 && gy < H && gx >= 0 && gx < W)
                v = xb[ci * HW + gy * W + gx];
            xs[i] = v;
        }
        for (int i = tid; i < 324; i += 256) {
            int oc = i / 12, j = i - oc * 12;
            ws[i] = (j < 9) ? w_off[oc * KDIM + ci * 9 + j] : 0.f;
        }
        __syncthreads();

        float xv[9];
#pragma unroll
        for (int ky = 0; ky < 3; ky++)
#pragma unroll
            for (int kx = 0; kx < 3; kx++)
                xv[ky * 3 + kx] = xs[(ty + ky) * 18 + tx + kx];

        const float4* w4 = (const float4*)ws;
#pragma unroll
        for (int oc = 0; oc < 27; oc++) {
            float4 a0 = w4[oc * 3 + 0], a1 = w4[oc * 3 + 1], a2 = w4[oc * 3 + 2];
            acc[oc] += xv[0] * a0.x + xv[1] * a0.y + xv[2] * a0.z + xv[3] * a0.w
                     + xv[4] * a1.x + xv[5] * a1.y + xv[6] * a1.z + xv[7] * a1.w
                     + xv[8] * a2.x;
        }
    }

    int pix = h * W + ww;
#pragma unroll
    for (int kk = 0; kk < 9; kk++) {
        float dy = acc[kk]      + b_off[kk];
        float dx = acc[9 + kk]  + b_off[9 + kk];
        float z  = acc[18 + kk] + b_off[18 + kk];
        float msk = 1.f / (1.f + __expf(-z));
        float py = (float)(h  + (kk / 3) - 1) + dy;
        float px = (float)(ww + (kk % 3) - 1) + dx;
        g_par[(b * 9 + kk) * HW + pix] = make_float4(py, px, msk, 0.f);
    }
}

// ======= Phase W: scaled weights, fragment-permuted within 32-k blocks ======
// pos(k) = kblock*32 + (k%4)*8 + (k%32)/4  -> thread q's 8 needed k's contiguous
__global__ void wt_kernel(const float* __restrict__ w,
                          const float* __restrict__ gamma,
                          const float* __restrict__ var)
{
    int co = blockIdx.x;
    float alpha = gamma[co] * rsqrtf(var[co] + EPSV);
    for (int k = threadIdx.x; k < KDIM; k += 256) {
        int pos = (k & ~31) + ((k & 3) << 3) + ((k & 31) >> 2);
        g_wB[co * KDIM + pos] = tf32_rna(w[co * KDIM + k] * alpha);
    }
}

// ============ Phase B: bilinear sampling -> g_valA[m][k] (pixel-major) ======
#define RS 76   // smem row stride (floats), multiple of 4 for float4 IO
__global__ __launch_bounds__(256) void sample_kernel(const float* __restrict__ x)
{
    __shared__ float sbuf[128 * RS];
    int m0 = blockIdx.x << 7;             // 128-pixel tile, within one batch image
    int b = m0 >> 12, pix0 = m0 & 4095;
    int tid = threadIdx.x;
    int p = tid >> 1, half = tid & 1;     // 2 threads per pixel
    int pix = pix0 + p;

    int   o00[9], o01[9], o10[9], o11[9];
    float t00[9], t01[9], t10[9], t11[9];
#pragma unroll
    for (int kk = 0; kk < 9; kk++) {
        float4 par = g_par[(b * 9 + kk) * HW + pix];
        float py = par.x, px = par.y, msk = par.z;
        float y0f = floorf(py), x0f = floorf(px);
        float wy = py - y0f, wx = px - x0f;
        int y0 = (int)y0f, x0 = (int)x0f;

        bool vy0 = (y0 >= 0)  && (y0 < H);
        bool vy1 = (y0 >= -1) && (y0 < H - 1);
        bool vx0 = (x0 >= 0)  && (x0 < W);
        bool vx1 = (x0 >= -1) && (x0 < W - 1);

        t00[kk] = (1.f - wy) * (1.f - wx) * msk * ((vy0 && vx0) ? 1.f : 0.f);
        t01[kk] = (1.f - wy) * wx         * msk * ((vy0 && vx1) ? 1.f : 0.f);
        t10[kk] = wy * (1.f - wx)         * msk * ((vy1 && vx0) ? 1.f : 0.f);
        t11[kk] = wy * wx                 * msk * ((vy1 && vx1) ? 1.f : 0.f);

        int y0c = min(max(y0, 0), H - 1), y1c = min(max(y0 + 1, 0), H - 1);
        int x0c = min(max(x0, 0), W - 1), x1c = min(max(x0 + 1, 0), W - 1);
        o00[kk] = y0c * W + x0c; o01[kk] = y0c * W + x1c;
        o10[kk] = y1c * W + x0c; o11[kk] = y1c * W + x1c;
    }

    const float* xb = x + b * (CI * HW);
    for (int g = 0; g < 32; g++) {        // ci groups of 8
#pragma unroll
        for (int cj = 0; cj < 4; cj++) {
            int ci = (g << 3) + (half << 2) + cj;
            const float* xp = xb + ci * HW;
            int colbase = half * 36 + cj * 9;
#pragma unroll
            for (int kk = 0; kk < 9; kk++) {
                float v = t00[kk] * xp[o00[kk]] + t01[kk] * xp[o01[kk]]
                        + t10[kk] * xp[o10[kk]] + t11[kk] * xp[o11[kk]];
                sbuf[p * RS + colbase + kk] = tf32_rna(v);
            }
        }
        __syncthreads();
        for (int i = tid; i < 128 * 18; i += 256) {   // 72 floats/row as 18 float4
            int row = i / 18, q = i - row * 18;
            float4 v = *(const float4*)&sbuf[row * RS + (q << 2)];
            *(float4*)&g_valA[(size_t)(m0 + row) * KDIM + g * 72 + (q << 2)] = v;
        }
        __syncthreads();
    }
}

// ============ Phase C: mma.sync tf32 GEMM + bias/BN-shift/ReLU ==============
// Block tile: M=128, N=256 (all Co), KC=32, double-buffered.
// 8 warps = 2(m) x 4(n); warp tile m64 x n64 -> acc[4][8][4] per thread.
#define KC     32
#define NSTG   72                 // 2304/32
#define SSTR   36                 // smem row stride (floats)
#define ASZ    (128 * SSTR)       // floats per A buffer
#define BSZ    (256 * SSTR)
#define DSMEM  ((2 * ASZ + 2 * BSZ) * 4)

__global__ __launch_bounds__(256, 1) void gemm_kernel(
    const float* __restrict__ bias,  const float* __restrict__ gamma,
    const float* __restrict__ beta,  const float* __restrict__ mean,
    const float* __restrict__ var,   float* __restrict__ out)
{
    extern __shared__ float dynf[];
    __shared__ float s_delta[CO];

    int tid  = threadIdx.x;
    int wid  = tid >> 5, lane = tid & 31;
    int gid  = lane >> 2, q = lane & 3;
    int wm   = wid & 1, wn = wid >> 1;

    float* As[2] = { dynf,           dynf + ASZ };
    float* Bs[2] = { dynf + 2 * ASZ, dynf + 2 * ASZ + BSZ };

    {   // folded epilogue constant per co
        float alpha = gamma[tid] * rsqrtf(var[tid] + EPSV);
        s_delta[tid] = fmaf(bias[tid] - mean[tid], alpha, beta[tid]);
    }

    int m0 = blockIdx.x << 7;

    float acc[4][8][4];
#pragma unroll
    for (int ma = 0; ma < 4; ma++)
#pragma unroll
        for (int na = 0; na < 8; na++)
#pragma unroll
            for (int e = 0; e < 4; e++) acc[ma][na][e] = 0.f;

    // ---- prologue: fill stage 0 into buffer 0 ----
    float4 av[4];
    {
        const int k0 = 0;
#pragma unroll
        for (int t = 0; t < 4; t++) {
            int idx4 = tid + (t << 8);
            int r = idx4 >> 3, c = idx4 & 7;
            av[t] = *(const float4*)&g_valA[(size_t)(m0 + r) * KDIM + k0 + (c << 2)];
        }
#pragma unroll
        for (int t = 0; t < 8; t++) {
            int idx4 = tid + (t << 8);
            int r = idx4 >> 3, c = idx4 & 7;
            cp_async16(smem_u32(&Bs[0][r * SSTR + (c << 2)]),
                       &g_wB[r * KDIM + k0 + (c << 2)]);
        }
        CP_COMMIT();
#pragma unroll
        for (int t = 0; t < 4; t++) {
            int idx4 = tid + (t << 8);
            int r = idx4 >> 3, c = idx4 & 7;
            As[0][r * SSTR + c]      = av[t].x;   // pos = (k%4)*8 + k/4
            As[0][r * SSTR + 8 + c]  = av[t].y;
            As[0][r * SSTR + 16 + c] = av[t].z;
            As[0][r * SSTR + 24 + c] = av[t].w;
        }
        CP_WAIT0();
    }
    __syncthreads();

    for (int s = 0; s < NSTG; s++) {
        int tb = s & 1, nb = tb ^ 1;
        if (s + 1 < NSTG) {
            const int k0 = (s + 1) * KC;
#pragma unroll
            for (int t = 0; t < 4; t++) {
                int idx4 = tid + (t << 8);
                int r = idx4 >> 3, c = idx4 & 7;
                av[t] = *(const float4*)&g_valA[(size_t)(m0 + r) * KDIM + k0 + (c << 2)];
            }
#pragma unroll
            for (int t = 0; t < 8; t++) {
                int idx4 = tid + (t << 8);
                int r = idx4 >> 3, c = idx4 & 7;
                cp_async16(smem_u32(&Bs[nb][r * SSTR + (c << 2)]),
                           &g_wB[r * KDIM + k0 + (c << 2)]);
            }
            CP_COMMIT();
        }

        // ---- compute current stage ----
        const float* Ab = As[tb];
        const float* Bb = Bs[tb];
#pragma unroll
        for (int j = 0; j < 4; j++) {
            uint32_t af[4][4];
#pragma unroll
            for (int ma = 0; ma < 4; ma++) {
                int r0 = wm * 64 + ma * 16 + gid;
                float2 v0 = *(const float2*)&Ab[r0 * SSTR + q * 8 + 2 * j];
                float2 v1 = *(const float2*)&Ab[(r0 + 8) * SSTR + q * 8 + 2 * j];
                af[ma][0] = __float_as_uint(v0.x);
                af[ma][1] = __float_as_uint(v1.x);
                af[ma][2] = __float_as_uint(v0.y);
                af[ma][3] = __float_as_uint(v1.y);
            }
#pragma unroll
            for (int na = 0; na < 8; na++) {
                int n = wn * 64 + na * 8 + gid;
                float2 bv = *(const float2*)&Bb[n * SSTR + q * 8 + 2 * j];
                uint32_t b0 = __float_as_uint(bv.x);
                uint32_t b1 = __float_as_uint(bv.y);
#pragma unroll
                for (int ma = 0; ma < 4; ma++)
                    mma_tf32(acc[ma][na][0], acc[ma][na][1], acc[ma][na][2], acc[ma][na][3],
                             af[ma][0], af[ma][1], af[ma][2], af[ma][3], b0, b1);
            }
        }

        if (s + 1 < NSTG) {
#pragma unroll
            for (int t = 0; t < 4; t++) {
                int idx4 = tid + (t << 8);
                int r = idx4 >> 3, c = idx4 & 7;
                As[nb][r * SSTR + c]      = av[t].x;
                As[nb][r * SSTR + 8 + c]  = av[t].y;
                As[nb][r * SSTR + 16 + c] = av[t].z;
                As[nb][r * SSTR + 24 + c] = av[t].w;
            }
            CP_WAIT0();
        }
        __syncthreads();
    }

    // ---- epilogue ----
    int b   = m0 >> 12;
    int hw0 = m0 & 4095;
    float* ob = out + b * (CO * HW);
#pragma unroll
    for (int ma = 0; ma < 4; ma++) {
#pragma unroll
        for (int na = 0; na < 8; na++) {
#pragma unroll
            for (int e = 0; e < 4; e++) {
                int row = wm * 64 + ma * 16 + gid + ((e >> 1) << 3);
                int co  = wn * 64 + na * 8 + (q << 1) + (e & 1);
                float v = acc[ma][na][e] + s_delta[co];
                ob[co * HW + hw0 + row] = fmaxf(v, 0.f);
            }
        }
    }
}

// ===========================================================================
extern "C" void kernel_launch(void* const* d_in, const int* in_sizes, int n_in,
                              void* d_out, int out_size)
{
    const float* x     = (const float*)d_in[0];
    const float* w_off = (const float*)d_in[1];
    const float* b_off = (const float*)d_in[2];
    const float* w     = (const float*)d_in[3];
    const float* bias  = (const float*)d_in[4];
    const float* gamma = (const float*)d_in[5];
    const float* beta  = (const float*)d_in[6];
    const float* mean  = (const float*)d_in[7];
    const float* var   = (const float*)d_in[8];
    float* out = (float*)d_out;

    cudaFuncSetAttribute(gemm_kernel, cudaFuncAttributeMaxDynamicSharedMemorySize, DSMEM);

    offset_kernel<<<dim3(16, 8), 256>>>(x, w_off, b_off);
    wt_kernel<<<CO, 256>>>(w, gamma, var);
    sample_kernel<<<M_TOT / 128, 256>>>(x);
    gemm_kernel<<<M_TOT / 128, 256, DSMEM>>>(bias, gamma, beta, mean, var, out);
}

// round 10
// speedup vs baseline: 2.0081x; 1.5366x over previous
#include <cuda_runtime.h>
#include <math.h>
#include <stdint.h>

#define BATCH 8
#define CI    256
#define CO    256
#define H     64
#define W     64
#define HW    4096
#define M_TOT 32768          // BATCH*HW
#define KDIM  2304           // CI*9
#define EPSV  1e-5f

// ---------------- scratch (__device__ globals: allocation-free rule) -------
__device__ float  g_valA[(size_t)M_TOT * KDIM]; // [m][k perm8], tf32-rounded (302 MB)
__device__ float  g_om[108 * M_TOT];            // offset-conv partials [chunk*27+oc][m]
__device__ float4 g_par[BATCH * 9 * HW];        // (py, px, mask, -) per (b,kk,pixel)
__device__ float  g_wB[CO * KDIM];              // [co][k perm8], w*bn_scale, tf32-rounded

// k-permutation within 8-blocks: layout [k0,k4,k1,k5,k2,k6,k3,k7]
// pos(k)  = (k&~7) + ((k&3)<<1) + ((k&7)>>2)
// kinv(p) = (p&~7) + ((p&7)>>1) + ((p&1)<<2)
__device__ __forceinline__ int p8inv(int p) {
    return (p & ~7) + ((p & 7) >> 1) + ((p & 1) << 2);
}

// ===================== small helpers ========================================
__device__ __forceinline__ uint32_t smem_u32(const void* p) {
    uint32_t a;
    asm("{ .reg .u64 t; cvta.to.shared.u64 t, %1; cvt.u32.u64 %0, t; }" : "=r"(a) : "l"(p));
    return a;
}
__device__ __forceinline__ float tf32_rna(float v) {
    uint32_t u;
    asm("cvt.rna.tf32.f32 %0, %1;" : "=r"(u) : "f"(v));
    return __uint_as_float(u);
}
__device__ __forceinline__ void cp_async16(uint32_t dst, const void* src) {
    asm volatile("cp.async.cg.shared.global [%0], [%1], 16;" :: "r"(dst), "l"(src) : "memory");
}
#define CP_COMMIT() asm volatile("cp.async.commit_group;" ::: "memory")
#define CP_WAIT2()  asm volatile("cp.async.wait_group 2;" ::: "memory")

__device__ __forceinline__ void mma_tf32(float& c0, float& c1, float& c2, float& c3,
                                         uint32_t a0, uint32_t a1, uint32_t a2, uint32_t a3,
                                         uint32_t b0, uint32_t b1) {
    asm volatile(
        "mma.sync.aligned.m16n8k8.row.col.f32.tf32.tf32.f32 "
        "{%0,%1,%2,%3}, {%4,%5,%6,%7}, {%8,%9}, {%0,%1,%2,%3};"
        : "+f"(c0), "+f"(c1), "+f"(c2), "+f"(c3)
        : "r"(a0), "r"(a1), "r"(a2), "r"(a3), "r"(b0), "r"(b1));
}

// ============ Phase A1: offset conv partials (4-way ci split) ===============
__global__ __launch_bounds__(256) void offset_kernel(
    const float* __restrict__ x, const float* __restrict__ w_off)
{
    __shared__ float  xs[18 * 18];
    __shared__ float4 ws4[81];                 // [27][12] padded weights
    float* ws = (float*)ws4;

    int b     = blockIdx.y;
    int chunk = blockIdx.z;                    // ci chunk of 64
    int tile  = blockIdx.x;                    // 16 tiles of 16x16
    int h0 = (tile >> 2) << 4;
    int w0 = (tile & 3) << 4;
    int tid = threadIdx.x;
    int ty = tid >> 4, tx = tid & 15;
    int h = h0 + ty, ww = w0 + tx;

    float acc[27];
#pragma unroll
    for (int i = 0; i < 27; i++) acc[i] = 0.f;

    const float* xb = x + b * (CI * HW);
    int ci0 = chunk << 6;
    for (int cit = 0; cit < 64; cit++) {
        int ci = ci0 + cit;
        __syncthreads();
        for (int i = tid; i < 324; i += 256) {
            int r = i / 18, c = i - r * 18;
            int gy = h0 + r - 1, gx = w0 + c - 1;
            float v = 0.f;
            if (gy >= 0 && gy < H && gx >= 0 && gx < W)
                v = xb[ci * HW + gy * W + gx];
            xs[i] = v;
        }
        for (int i = tid; i < 324; i += 256) {
            int oc = i / 12, j = i - oc * 12;
            ws[i] = (j < 9) ? w_off[oc * KDIM + ci * 9 + j] : 0.f;
        }
        __syncthreads();

        float xv[9];
#pragma unroll
        for (int ky = 0; ky < 3; ky++)
#pragma unroll
            for (int kx = 0; kx < 3; kx++)
                xv[ky * 3 + kx] = xs[(ty + ky) * 18 + tx + kx];

        const float4* w4 = (const float4*)ws;
#pragma unroll
        for (int oc = 0; oc < 27; oc++) {
            float4 a0 = w4[oc * 3 + 0], a1 = w4[oc * 3 + 1], a2 = w4[oc * 3 + 2];
            acc[oc] += xv[0] * a0.x + xv[1] * a0.y + xv[2] * a0.z + xv[3] * a0.w
                     + xv[4] * a1.x + xv[5] * a1.y + xv[6] * a1.z + xv[7] * a1.w
                     + xv[8] * a2.x;
        }
    }

    int m = b * HW + h * W + ww;
#pragma unroll
    for (int oc = 0; oc < 27; oc++)
        g_om[(chunk * 27 + oc) * M_TOT + m] = acc[oc];
}

// ============ Phase A2: reduce partials -> bilinear params ==================
__global__ __launch_bounds__(256) void reduce_kernel(const float* __restrict__ b_off)
{
    int m = blockIdx.x * 256 + threadIdx.x;
    int b = m >> 12, pix = m & 4095;
    int h = pix >> 6, ww = pix & 63;

    float om[27];
#pragma unroll
    for (int oc = 0; oc < 27; oc++) {
        float s = b_off[oc];
#pragma unroll
        for (int c = 0; c < 4; c++)
            s += g_om[(c * 27 + oc) * M_TOT + m];
        om[oc] = s;
    }
#pragma unroll
    for (int kk = 0; kk < 9; kk++) {
        float msk = 1.f / (1.f + __expf(-om[18 + kk]));
        float py = (float)(h  + (kk / 3) - 1) + om[kk];
        float px = (float)(ww + (kk % 3) - 1) + om[9 + kk];
        g_par[(b * 9 + kk) * HW + pix] = make_float4(py, px, msk, 0.f);
    }
}

// ======= Phase W: scaled weights, perm8-laid-out =============================
__global__ void wt_kernel(const float* __restrict__ w,
                          const float* __restrict__ gamma,
                          const float* __restrict__ var)
{
    int co = blockIdx.x;
    float alpha = gamma[co] * rsqrtf(var[co] + EPSV);
    for (int k = threadIdx.x; k < KDIM; k += 256) {
        int pos = (k & ~7) + ((k & 3) << 1) + ((k & 7) >> 2);
        g_wB[co * KDIM + pos] = tf32_rna(w[co * KDIM + k] * alpha);
    }
}

// ============ Phase B: bilinear sampling -> g_valA[m][k perm8] ==============
#define RS 76   // smem row stride (floats)
__global__ __launch_bounds__(256) void sample_kernel(const float* __restrict__ x)
{
    __shared__ float sbuf[128 * RS];
    int m0 = blockIdx.x << 7;             // 128-pixel tile, within one batch image
    int b = m0 >> 12, pix0 = m0 & 4095;
    int tid = threadIdx.x;
    int p = tid >> 1, half = tid & 1;     // 2 threads per pixel
    int pix = pix0 + p;

    int    base[9];
    float4 wq[9];                         // (w00, w01, w10, w11) fused with mask
#pragma unroll
    for (int kk = 0; kk < 9; kk++) {
        float4 par = g_par[(b * 9 + kk) * HW + pix];
        float py = par.x, px = par.y, msk = par.z;
        float y0f = floorf(py), x0f = floorf(px);
        float wy = py - y0f, wx = px - x0f;
        int y0 = (int)y0f, x0 = (int)x0f;

        int yT = min(max(y0, 0), H - 2);
        int xL = min(max(x0, 0), W - 2);
        // per-axis pair weights with validity folded (equals reference's 4 masked corners)
        float wyt = (yT == y0) ? (1.f - wy) : ((yT == y0 + 1) ? wy : 0.f);
        float wyb = (yT + 1 == y0) ? (1.f - wy) : ((yT == y0) ? wy : 0.f);
        float wxl = (xL == x0) ? (1.f - wx) : ((xL == x0 + 1) ? wx : 0.f);
        float wxr = (xL + 1 == x0) ? (1.f - wx) : ((xL == x0) ? wx : 0.f);
        wyt *= msk; wyb *= msk;

        base[kk] = yT * W + xL;
        wq[kk] = make_float4(wyt * wxl, wyt * wxr, wyb * wxl, wyb * wxr);
    }

    const float* xb = x + b * (CI * HW);
    for (int g = 0; g < 32; g++) {        // ci groups of 8
#pragma unroll
        for (int cj = 0; cj < 4; cj++) {
            int ci = (g << 3) + (half << 2) + cj;
            const float* xp = xb + ci * HW;
            int colbase = half * 36 + cj * 9;
#pragma unroll
            for (int kk = 0; kk < 9; kk++) {
                const float* pb = xp + base[kk];
                float4 wv = wq[kk];
                float v = wv.x * pb[0] + wv.y * pb[1]
                        + wv.z * pb[W] + wv.w * pb[W + 1];
                sbuf[p * RS + colbase + kk] = tf32_rna(v);
            }
        }
        __syncthreads();
        // write 72 k's per row as 18 float4, perm8 layout in gmem
        for (int i = tid; i < 128 * 18; i += 256) {
            int row = i / 18, t = i - row * 18;
            int p0 = t << 2;
            const float* sr = &sbuf[row * RS];
            float4 v;
            v.x = sr[p8inv(p0 + 0)];
            v.y = sr[p8inv(p0 + 1)];
            v.z = sr[p8inv(p0 + 2)];
            v.w = sr[p8inv(p0 + 3)];
            *(float4*)&g_valA[(size_t)(m0 + row) * KDIM + g * 72 + p0] = v;
        }
        __syncthreads();
    }
}

// ============ Phase C: mma.sync tf32 GEMM + bias/BN-shift/ReLU ==============
// Block: M=128, N=256, KC=32; 512 threads = 16 warps as 4(m) x 4(n);
// warp tile m32 x n64 -> acc[2][8][4]. 3-stage cp.async pipeline, A and B.
#define KC     32
#define NSTG   72                 // 2304/32
#define SSTR   36                 // smem row stride (floats)
#define ASZ    (128 * SSTR)
#define BSZ    (256 * SSTR)
#define NBUF   3
#define DSMEM  ((ASZ + BSZ) * NBUF * 4)

__global__ __launch_bounds__(512, 1) void gemm_kernel(
    const float* __restrict__ bias,  const float* __restrict__ gamma,
    const float* __restrict__ beta,  const float* __restrict__ mean,
    const float* __restrict__ var,   float* __restrict__ out)
{
    extern __shared__ float dynf[];
    __shared__ float s_delta[CO];

    int tid  = threadIdx.x;
    int wid  = tid >> 5, lane = tid & 31;
    int gid  = lane >> 2, q = lane & 3;
    int wm   = wid & 3, wn = wid >> 2;

    float* As[NBUF];
    float* Bs[NBUF];
#pragma unroll
    for (int i = 0; i < NBUF; i++) {
        As[i] = dynf + i * (ASZ + BSZ);
        Bs[i] = As[i] + ASZ;
    }

    if (tid < 256) {
        float alpha = gamma[tid] * rsqrtf(var[tid] + EPSV);
        s_delta[tid] = fmaf(bias[tid] - mean[tid], alpha, beta[tid]);
    }

    int m0 = blockIdx.x << 7;

    float acc[2][8][4];
#pragma unroll
    for (int ma = 0; ma < 2; ma++)
#pragma unroll
        for (int na = 0; na < 8; na++)
#pragma unroll
            for (int e = 0; e < 4; e++) acc[ma][na][e] = 0.f;

#define FILL(sidx, buf) do {                                                   \
    const int k0 = (sidx) * KC;                                                \
    _Pragma("unroll")                                                          \
    for (int t = 0; t < 2; t++) {                                              \
        int idx4 = tid + (t << 9);                                             \
        int r = idx4 >> 3, c = idx4 & 7;                                       \
        cp_async16(smem_u32(&As[buf][r * SSTR + (c << 2)]),                    \
                   &g_valA[(size_t)(m0 + r) * KDIM + k0 + (c << 2)]);          \
    }                                                                          \
    _Pragma("unroll")                                                          \
    for (int t = 0; t < 4; t++) {                                              \
        int idx4 = tid + (t << 9);                                             \
        int r = idx4 >> 3, c = idx4 & 7;                                       \
        cp_async16(smem_u32(&Bs[buf][r * SSTR + (c << 2)]),                    \
                   &g_wB[r * KDIM + k0 + (c << 2)]);                           \
    }                                                                          \
} while (0)

    FILL(0, 0); CP_COMMIT();
    FILL(1, 1); CP_COMMIT();

    for (int s = 0; s < NSTG; s++) {
        int buf = s % NBUF;
        if (s + 2 < NSTG) {
            int nb = (s + 2) % NBUF;
            FILL(s + 2, nb);
        }
        CP_COMMIT();               // uniform group count (may be empty at tail)
        CP_WAIT2();                // oldest group (stage s) complete
        __syncthreads();

        const float* Ab = As[buf];
        const float* Bb = Bs[buf];
#pragma unroll
        for (int j = 0; j < 4; j++) {
            uint32_t af[2][4];
#pragma unroll
            for (int ma = 0; ma < 2; ma++) {
                int r0 = wm * 32 + ma * 16 + gid;
                float2 v0 = *(const float2*)&Ab[r0 * SSTR + j * 8 + q * 2];
                float2 v1 = *(const float2*)&Ab[(r0 + 8) * SSTR + j * 8 + q * 2];
                af[ma][0] = __float_as_uint(v0.x);
                af[ma][1] = __float_as_uint(v1.x);
                af[ma][2] = __float_as_uint(v0.y);
                af[ma][3] = __float_as_uint(v1.y);
            }
#pragma unroll
            for (int na = 0; na < 8; na++) {
                int n = wn * 64 + na * 8 + gid;
                float2 bv = *(const float2*)&Bb[n * SSTR + j * 8 + q * 2];
                uint32_t b0 = __float_as_uint(bv.x);
                uint32_t b1 = __float_as_uint(bv.y);
#pragma unroll
                for (int ma = 0; ma < 2; ma++)
                    mma_tf32(acc[ma][na][0], acc[ma][na][1], acc[ma][na][2], acc[ma][na][3],
                             af[ma][0], af[ma][1], af[ma][2], af[ma][3], b0, b1);
            }
        }
        __syncthreads();           // buffer reuse safety for next FILL
    }

    // ---- epilogue ----
    int b   = m0 >> 12;
    int hw0 = m0 & 4095;
    float* ob = out + b * (CO * HW);
#pragma unroll
    for (int ma = 0; ma < 2; ma++) {
#pragma unroll
        for (int na = 0; na < 8; na++) {
#pragma unroll
            for (int e = 0; e < 4; e++) {
                int row = wm * 32 + ma * 16 + gid + ((e >> 1) << 3);
                int co  = wn * 64 + na * 8 + (q << 1) + (e & 1);
                float v = acc[ma][na][e] + s_delta[co];
                ob[co * HW + hw0 + row] = fmaxf(v, 0.f);
            }
        }
    }
}

// ===========================================================================
extern "C" void kernel_launch(void* const* d_in, const int* in_sizes, int n_in,
                              void* d_out, int out_size)
{
    const float* x     = (const float*)d_in[0];
    const float* w_off = (const float*)d_in[1];
    const float* b_off = (const float*)d_in[2];
    const float* w     = (const float*)d_in[3];
    const float* bias  = (const float*)d_in[4];
    const float* gamma = (const float*)d_in[5];
    const float* beta  = (const float*)d_in[6];
    const float* mean  = (const float*)d_in[7];
    const float* var   = (const float*)d_in[8];
    float* out = (float*)d_out;

    cudaFuncSetAttribute(gemm_kernel, cudaFuncAttributeMaxDynamicSharedMemorySize, DSMEM);

    offset_kernel<<<dim3(16, 8, 4), 256>>>(x, w_off);
    reduce_kernel<<<M_TOT / 256, 256>>>(b_off);
    wt_kernel<<<CO, 256>>>(w, gamma, var);
    sample_kernel<<<M_TOT / 128, 256>>>(x);
    gemm_kernel<<<M_TOT / 128, 512, DSMEM>>>(bias, gamma, beta, mean, var, out);
}

// round 11
// speedup vs baseline: 2.3317x; 1.1611x over previous
#include <cuda_runtime.h>
#include <math.h>
#include <stdint.h>

#define BATCH 8
#define CI    256
#define CO    256
#define H     64
#define W     64
#define HW    4096
#define M_TOT 32768          // BATCH*HW
#define KDIM  2304           // CI*9
#define EPSV  1e-5f

// ---------------- scratch (__device__ globals: allocation-free rule) -------
__device__ float  g_valA[(size_t)M_TOT * KDIM]; // [m][k perm8], tf32-rounded (302 MB)
__device__ float  g_xT[(size_t)BATCH * HW * CI];// x transposed: [b][pix][ci] (134 MB)
__device__ float  g_om[108 * M_TOT];            // offset-conv partials [chunk*27+oc][m]
__device__ float4 g_par[BATCH * 9 * HW];        // (py, px, mask, -) per (b,kk,pixel)
__device__ float  g_wB[CO * KDIM];              // [co][k perm8], w*bn_scale, tf32-rounded

// k-permutation within 8-blocks: layout [k0,k4,k1,k5,k2,k6,k3,k7]
// pos(k)  = (k&~7) + ((k&3)<<1) + ((k&7)>>2)
// kinv(p) = (p&~7) + ((p&7)>>1) + ((p&1)<<2)
__device__ __forceinline__ int p8inv(int p) {
    return (p & ~7) + ((p & 7) >> 1) + ((p & 1) << 2);
}

// ===================== small helpers ========================================
__device__ __forceinline__ uint32_t smem_u32(const void* p) {
    uint32_t a;
    asm("{ .reg .u64 t; cvta.to.shared.u64 t, %1; cvt.u32.u64 %0, t; }" : "=r"(a) : "l"(p));
    return a;
}
__device__ __forceinline__ float tf32_rna(float v) {
    uint32_t u;
    asm("cvt.rna.tf32.f32 %0, %1;" : "=r"(u) : "f"(v));
    return __uint_as_float(u);
}
__device__ __forceinline__ void cp_async16(uint32_t dst, const void* src) {
    asm volatile("cp.async.cg.shared.global [%0], [%1], 16;" :: "r"(dst), "l"(src) : "memory");
}
#define CP_COMMIT() asm volatile("cp.async.commit_group;" ::: "memory")
#define CP_WAIT2()  asm volatile("cp.async.wait_group 2;" ::: "memory")

__device__ __forceinline__ void mma_tf32(float& c0, float& c1, float& c2, float& c3,
                                         uint32_t a0, uint32_t a1, uint32_t a2, uint32_t a3,
                                         uint32_t b0, uint32_t b1) {
    asm volatile(
        "mma.sync.aligned.m16n8k8.row.col.f32.tf32.tf32.f32 "
        "{%0,%1,%2,%3}, {%4,%5,%6,%7}, {%8,%9}, {%0,%1,%2,%3};"
        : "+f"(c0), "+f"(c1), "+f"(c2), "+f"(c3)
        : "r"(a0), "r"(a1), "r"(a2), "r"(a3), "r"(b0), "r"(b1));
}

// ============ Phase T: NCHW -> NHWC transpose (x -> g_xT) ===================
__global__ __launch_bounds__(256) void transpose_kernel(const float* __restrict__ x)
{
    __shared__ float s[32][33];
    int b    = blockIdx.z;
    int ci0  = blockIdx.y << 5;
    int pix0 = blockIdx.x << 5;
    int tid = threadIdx.x;
    int r = tid >> 5, c = tid & 31;

    const float* xb = x + (size_t)b * CI * HW;
#pragma unroll
    for (int rr = 0; rr < 4; rr++) {
        int ci = ci0 + r + (rr << 3);
        s[r + (rr << 3)][c] = xb[(size_t)ci * HW + pix0 + c];
    }
    __syncthreads();
    float* xT = g_xT + (size_t)b * HW * CI;
#pragma unroll
    for (int rr = 0; rr < 4; rr++) {
        int pix = pix0 + r + (rr << 3);
        xT[(size_t)pix * CI + ci0 + c] = s[c][r + (rr << 3)];
    }
}

// ============ Phase A1: offset conv partials (4-way ci split) ===============
__global__ __launch_bounds__(256) void offset_kernel(
    const float* __restrict__ x, const float* __restrict__ w_off)
{
    __shared__ float  xs[18 * 18];
    __shared__ float4 ws4[81];                 // [27][12] padded weights
    float* ws = (float*)ws4;

    int b     = blockIdx.y;
    int chunk = blockIdx.z;                    // ci chunk of 64
    int tile  = blockIdx.x;                    // 16 tiles of 16x16
    int h0 = (tile >> 2) << 4;
    int w0 = (tile & 3) << 4;
    int tid = threadIdx.x;
    int ty = tid >> 4, tx = tid & 15;
    int h = h0 + ty, ww = w0 + tx;

    float acc[27];
#pragma unroll
    for (int i = 0; i < 27; i++) acc[i] = 0.f;

    const float* xb = x + b * (CI * HW);
    int ci0 = chunk << 6;
    for (int cit = 0; cit < 64; cit++) {
        int ci = ci0 + cit;
        __syncthreads();
        for (int i = tid; i < 324; i += 256) {
            int r = i / 18, c = i - r * 18;
            int gy = h0 + r - 1, gx = w0 + c - 1;
            float v = 0.f;
            if (gy >= 0 && gy < H && gx >= 0 && gx < W)
                v = xb[ci * HW + gy * W + gx];
            xs[i] = v;
        }
        for (int i = tid; i < 324; i += 256) {
            int oc = i / 12, j = i - oc * 12;
            ws[i] = (j < 9) ? w_off[oc * KDIM + ci * 9 + j] : 0.f;
        }
        __syncthreads();

        float xv[9];
#pragma unroll
        for (int ky = 0; ky < 3; ky++)
#pragma unroll
            for (int kx = 0; kx < 3; kx++)
                xv[ky * 3 + kx] = xs[(ty + ky) * 18 + tx + kx];

        const float4* w4 = (const float4*)ws;
#pragma unroll
        for (int oc = 0; oc < 27; oc++) {
            float4 a0 = w4[oc * 3 + 0], a1 = w4[oc * 3 + 1], a2 = w4[oc * 3 + 2];
            acc[oc] += xv[0] * a0.x + xv[1] * a0.y + xv[2] * a0.z + xv[3] * a0.w
                     + xv[4] * a1.x + xv[5] * a1.y + xv[6] * a1.z + xv[7] * a1.w
                     + xv[8] * a2.x;
        }
    }

    int m = b * HW + h * W + ww;
#pragma unroll
    for (int oc = 0; oc < 27; oc++)
        g_om[(chunk * 27 + oc) * M_TOT + m] = acc[oc];
}

// ============ Phase A2: reduce partials -> bilinear params ==================
__global__ __launch_bounds__(256) void reduce_kernel(const float* __restrict__ b_off)
{
    int m = blockIdx.x * 256 + threadIdx.x;
    int b = m >> 12, pix = m & 4095;
    int h = pix >> 6, ww = pix & 63;

    float om[27];
#pragma unroll
    for (int oc = 0; oc < 27; oc++) {
        float s = b_off[oc];
#pragma unroll
        for (int c = 0; c < 4; c++)
            s += g_om[(c * 27 + oc) * M_TOT + m];
        om[oc] = s;
    }
#pragma unroll
    for (int kk = 0; kk < 9; kk++) {
        float msk = 1.f / (1.f + __expf(-om[18 + kk]));
        float py = (float)(h  + (kk / 3) - 1) + om[kk];
        float px = (float)(ww + (kk % 3) - 1) + om[9 + kk];
        g_par[(b * 9 + kk) * HW + pix] = make_float4(py, px, msk, 0.f);
    }
}

// ======= Phase W: scaled weights, perm8-laid-out =============================
__global__ void wt_kernel(const float* __restrict__ w,
                          const float* __restrict__ gamma,
                          const float* __restrict__ var)
{
    int co = blockIdx.x;
    float alpha = gamma[co] * rsqrtf(var[co] + EPSV);
    for (int k = threadIdx.x; k < KDIM; k += 256) {
        int pos = (k & ~7) + ((k & 3) << 1) + ((k & 7) >> 2);
        g_wB[co * KDIM + pos] = tf32_rna(w[co * KDIM + k] * alpha);
    }
}

// ============ Phase B: bilinear sampling (NHWC) -> g_valA[m][k perm8] =======
// One warp per pixel (8 pixels / 256-thread block). Lane <-> ci quad:
// every corner read is a 512B fully-coalesced float4 load from g_xT.
__global__ __launch_bounds__(256) void sample_kernel()
{
    __shared__ float sbuf[8 * 9 * 132];       // [pix][kk][128ci + 4 pad] = 38016 B
    int tid  = threadIdx.x;
    int warp = tid >> 5, lane = tid & 31;
    int m0 = blockIdx.x << 3;                 // 8 pixels per block
    int m  = m0 + warp;
    int b = m >> 12, pix = m & 4095;

    int    base[9];
    float4 wq[9];                             // (w00, w01, w10, w11) fused with mask
#pragma unroll
    for (int kk = 0; kk < 9; kk++) {
        float4 par = g_par[(b * 9 + kk) * HW + pix];   // warp-uniform broadcast
        float py = par.x, px = par.y, msk = par.z;
        float y0f = floorf(py), x0f = floorf(px);
        float wy = py - y0f, wx = px - x0f;
        int y0 = (int)y0f, x0 = (int)x0f;

        int yT = min(max(y0, 0), H - 2);
        int xL = min(max(x0, 0), W - 2);
        float wyt = (yT == y0) ? (1.f - wy) : ((yT == y0 + 1) ? wy : 0.f);
        float wyb = (yT + 1 == y0) ? (1.f - wy) : ((yT == y0) ? wy : 0.f);
        float wxl = (xL == x0) ? (1.f - wx) : ((xL == x0 + 1) ? wx : 0.f);
        float wxr = (xL + 1 == x0) ? (1.f - wx) : ((xL == x0) ? wx : 0.f);
        wyt *= msk; wyb *= msk;

        base[kk] = yT * W + xL;
        wq[kk] = make_float4(wyt * wxl, wyt * wxr, wyb * wxl, wyb * wxr);
    }

    const float* xTb = g_xT + (size_t)b * HW * CI;
    float4* sb4 = (float4*)sbuf;

    for (int half = 0; half < 2; half++) {
        int ci0 = (half << 7) + (lane << 2);
#pragma unroll
        for (int kk = 0; kk < 9; kk++) {
            const float* p00 = xTb + (size_t)base[kk] * CI + ci0;
            float4 a  = *(const float4*)(p00);
            float4 bq = *(const float4*)(p00 + CI);
            float4 c  = *(const float4*)(p00 + W * CI);
            float4 d  = *(const float4*)(p00 + (W + 1) * CI);
            float4 wv = wq[kk];
            float4 v;
            v.x = tf32_rna(wv.x * a.x + wv.y * bq.x + wv.z * c.x + wv.w * d.x);
            v.y = tf32_rna(wv.x * a.y + wv.y * bq.y + wv.z * c.y + wv.w * d.y);
            v.z = tf32_rna(wv.x * a.z + wv.y * bq.z + wv.z * c.z + wv.w * d.z);
            v.w = tf32_rna(wv.x * a.w + wv.y * bq.w + wv.z * c.w + wv.w * d.w);
            sb4[(warp * 9 + kk) * 33 + lane] = v;      // STS.128, conflict-free
        }
        __syncthreads();
        // write half (1152 k per pixel) to gmem in perm8 layout, coalesced
#pragma unroll
        for (int t = 0; t < 9; t++) {
            int i  = tid + (t << 8);          // 0..2303 (float4 units this half)
            int pw = i / 288;
            int p0 = (i - pw * 288) << 2;     // local perm position
            float4 v;
#pragma unroll
            for (int j = 0; j < 4; j++) {
                int kl  = p8inv(p0 + j);
                int cil = kl / 9;
                int kk  = kl - cil * 9;
                ((float*)&v)[j] = sbuf[(pw * 9 + kk) * 132 + cil];
            }
            *(float4*)&g_valA[(size_t)(m0 + pw) * KDIM + half * 1152 + p0] = v;
        }
        __syncthreads();
    }
}

// ============ Phase C: mma.sync tf32 GEMM + bias/BN-shift/ReLU ==============
// Block: M=128, N=256, KC=32; 512 threads = 16 warps as 4(m) x 4(n);
// warp tile m32 x n64 -> acc[2][8][4]. 3-stage cp.async pipeline, A and B.
#define KC     32
#define NSTG   72                 // 2304/32
#define SSTR   36                 // smem row stride (floats)
#define ASZ    (128 * SSTR)
#define BSZ    (256 * SSTR)
#define NBUF   3
#define DSMEM  ((ASZ + BSZ) * NBUF * 4)

__global__ __launch_bounds__(512, 1) void gemm_kernel(
    const float* __restrict__ bias,  const float* __restrict__ gamma,
    const float* __restrict__ beta,  const float* __restrict__ mean,
    const float* __restrict__ var,   float* __restrict__ out)
{
    extern __shared__ float dynf[];
    __shared__ float s_delta[CO];

    int tid  = threadIdx.x;
    int wid  = tid >> 5, lane = tid & 31;
    int gid  = lane >> 2, q = lane & 3;
    int wm   = wid & 3, wn = wid >> 2;

    float* As[NBUF];
    float* Bs[NBUF];
#pragma unroll
    for (int i = 0; i < NBUF; i++) {
        As[i] = dynf + i * (ASZ + BSZ);
        Bs[i] = As[i] + ASZ;
    }

    if (tid < 256) {
        float alpha = gamma[tid] * rsqrtf(var[tid] + EPSV);
        s_delta[tid] = fmaf(bias[tid] - mean[tid], alpha, beta[tid]);
    }

    int m0 = blockIdx.x << 7;

    float acc[2][8][4];
#pragma unroll
    for (int ma = 0; ma < 2; ma++)
#pragma unroll
        for (int na = 0; na < 8; na++)
#pragma unroll
            for (int e = 0; e < 4; e++) acc[ma][na][e] = 0.f;

#define FILL(sidx, buf) do {                                                   \
    const int k0 = (sidx) * KC;                                                \
    _Pragma("unroll")                                                          \
    for (int t = 0; t < 2; t++) {                                              \
        int idx4 = tid + (t << 9);                                             \
        int r = idx4 >> 3, c = idx4 & 7;                                       \
        cp_async16(smem_u32(&As[buf][r * SSTR + (c << 2)]),                    \
                   &g_valA[(size_t)(m0 + r) * KDIM + k0 + (c << 2)]);          \
    }                                                                          \
    _Pragma("unroll")                                                          \
    for (int t = 0; t < 4; t++) {                                              \
        int idx4 = tid + (t << 9);                                             \
        int r = idx4 >> 3, c = idx4 & 7;                                       \
        cp_async16(smem_u32(&Bs[buf][r * SSTR + (c << 2)]),                    \
                   &g_wB[r * KDIM + k0 + (c << 2)]);                           \
    }                                                                          \
} while (0)

    FILL(0, 0); CP_COMMIT();
    FILL(1, 1); CP_COMMIT();

    for (int s = 0; s < NSTG; s++) {
        int buf = s % NBUF;
        if (s + 2 < NSTG) {
            int nb = (s + 2) % NBUF;
            FILL(s + 2, nb);
        }
        CP_COMMIT();               // uniform group count (may be empty at tail)
        CP_WAIT2();                // oldest group (stage s) complete
        __syncthreads();

        const float* Ab = As[buf];
        const float* Bb = Bs[buf];
#pragma unroll
        for (int j = 0; j < 4; j++) {
            uint32_t af[2][4];
#pragma unroll
            for (int ma = 0; ma < 2; ma++) {
                int r0 = wm * 32 + ma * 16 + gid;
                float2 v0 = *(const float2*)&Ab[r0 * SSTR + j * 8 + q * 2];
                float2 v1 = *(const float2*)&Ab[(r0 + 8) * SSTR + j * 8 + q * 2];
                af[ma][0] = __float_as_uint(v0.x);
                af[ma][1] = __float_as_uint(v1.x);
                af[ma][2] = __float_as_uint(v0.y);
                af[ma][3] = __float_as_uint(v1.y);
            }
#pragma unroll
            for (int na = 0; na < 8; na++) {
                int n = wn * 64 + na * 8 + gid;
                float2 bv = *(const float2*)&Bb[n * SSTR + j * 8 + q * 2];
                uint32_t b0 = __float_as_uint(bv.x);
                uint32_t b1 = __float_as_uint(bv.y);
#pragma unroll
                for (int ma = 0; ma < 2; ma++)
                    mma_tf32(acc[ma][na][0], acc[ma][na][1], acc[ma][na][2], acc[ma][na][3],
                             af[ma][0], af[ma][1], af[ma][2], af[ma][3], b0, b1);
            }
        }
        __syncthreads();           // buffer reuse safety for next FILL
    }

    // ---- epilogue ----
    int b   = m0 >> 12;
    int hw0 = m0 & 4095;
    float* ob = out + b * (CO * HW);
#pragma unroll
    for (int ma = 0; ma < 2; ma++) {
#pragma unroll
        for (int na = 0; na < 8; na++) {
#pragma unroll
            for (int e = 0; e < 4; e++) {
                int row = wm * 32 + ma * 16 + gid + ((e >> 1) << 3);
                int co  = wn * 64 + na * 8 + (q << 1) + (e & 1);
                float v = acc[ma][na][e] + s_delta[co];
                ob[co * HW + hw0 + row] = fmaxf(v, 0.f);
            }
        }
    }
}

// ===========================================================================
extern "C" void kernel_launch(void* const* d_in, const int* in_sizes, int n_in,
                              void* d_out, int out_size)
{
    const float* x     = (const float*)d_in[0];
    const float* w_off = (const float*)d_in[1];
    const float* b_off = (const float*)d_in[2];
    const float* w     = (const float*)d_in[3];
    const float* bias  = (const float*)d_in[4];
    const float* gamma = (const float*)d_in[5];
    const float* beta  = (const float*)d_in[6];
    const float* mean  = (const float*)d_in[7];
    const float* var   = (const float*)d_in[8];
    float* out = (float*)d_out;

    cudaFuncSetAttribute(gemm_kernel, cudaFuncAttributeMaxDynamicSharedMemorySize, DSMEM);

    transpose_kernel<<<dim3(128, 8, 8), 256>>>(x);
    offset_kernel<<<dim3(16, 8, 4), 256>>>(x, w_off);
    reduce_kernel<<<M_TOT / 256, 256>>>(b_off);
    wt_kernel<<<CO, 256>>>(w, gamma, var);
    sample_kernel<<<M_TOT / 8, 256>>>();
    gemm_kernel<<<M_TOT / 128, 512, DSMEM>>>(bias, gamma, beta, mean, var, out);
}

// round 12
// speedup vs baseline: 2.3360x; 1.0018x over previous
#include <cuda_runtime.h>
#include <math.h>
#include <stdint.h>

#define BATCH 8
#define CI    256
#define CO    256
#define H     64
#define W     64
#define HW    4096
#define M_TOT 32768          // BATCH*HW
#define KDIM  2304           // CI*9
#define EPSV  1e-5f

// ---------------- scratch (__device__ globals: allocation-free rule) -------
__device__ float  g_valA[(size_t)M_TOT * KDIM]; // [m][k perm8], tf32-rounded (302 MB)
__device__ float  g_xT[(size_t)BATCH * HW * CI];// x transposed: [b][pix][ci] (134 MB)
__device__ float  g_om[108 * M_TOT];            // offset-conv partials [chunk*27+oc][m]
__device__ float4 g_par[BATCH * 9 * HW];        // (py, px, mask, -) per (b,kk,pixel)
__device__ float  g_wB[CO * KDIM];              // [co][k perm8], w*bn_scale, tf32-rounded

// k-permutation within 8-blocks: layout [k0,k4,k1,k5,k2,k6,k3,k7]
// pos(k)  = (k&~7) + ((k&3)<<1) + ((k&7)>>2)
// kinv(p) = (p&~7) + ((p&7)>>1) + ((p&1)<<2)
__device__ __forceinline__ int p8inv(int p) {
    return (p & ~7) + ((p & 7) >> 1) + ((p & 1) << 2);
}

// ===================== small helpers ========================================
__device__ __forceinline__ uint32_t smem_u32(const void* p) {
    uint32_t a;
    asm("{ .reg .u64 t; cvta.to.shared.u64 t, %1; cvt.u32.u64 %0, t; }" : "=r"(a) : "l"(p));
    return a;
}
__device__ __forceinline__ float tf32_rna(float v) {
    uint32_t u;
    asm("cvt.rna.tf32.f32 %0, %1;" : "=r"(u) : "f"(v));
    return __uint_as_float(u);
}
__device__ __forceinline__ void cp_async16(uint32_t dst, const void* src) {
    asm volatile("cp.async.cg.shared.global [%0], [%1], 16;" :: "r"(dst), "l"(src) : "memory");
}
#define CP_COMMIT() asm volatile("cp.async.commit_group;" ::: "memory")
#define CP_WAIT2()  asm volatile("cp.async.wait_group 2;" ::: "memory")

__device__ __forceinline__ void mma_tf32(float& c0, float& c1, float& c2, float& c3,
                                         uint32_t a0, uint32_t a1, uint32_t a2, uint32_t a3,
                                         uint32_t b0, uint32_t b1) {
    asm volatile(
        "mma.sync.aligned.m16n8k8.row.col.f32.tf32.tf32.f32 "
        "{%0,%1,%2,%3}, {%4,%5,%6,%7}, {%8,%9}, {%0,%1,%2,%3};"
        : "+f"(c0), "+f"(c1), "+f"(c2), "+f"(c3)
        : "r"(a0), "r"(a1), "r"(a2), "r"(a3), "r"(b0), "r"(b1));
}

// ============ Phase T: NCHW -> NHWC transpose (x -> g_xT) ===================
__global__ __launch_bounds__(256) void transpose_kernel(const float* __restrict__ x)
{
    __shared__ float s[32][33];
    int b    = blockIdx.z;
    int ci0  = blockIdx.y << 5;
    int pix0 = blockIdx.x << 5;
    int tid = threadIdx.x;
    int r = tid >> 5, c = tid & 31;

    const float* xb = x + (size_t)b * CI * HW;
#pragma unroll
    for (int rr = 0; rr < 4; rr++) {
        int ci = ci0 + r + (rr << 3);
        s[r + (rr << 3)][c] = xb[(size_t)ci * HW + pix0 + c];
    }
    __syncthreads();
    float* xT = g_xT + (size_t)b * HW * CI;
#pragma unroll
    for (int rr = 0; rr < 4; rr++) {
        int pix = pix0 + r + (rr << 3);
        xT[(size_t)pix * CI + ci0 + c] = s[c][r + (rr << 3)];
    }
}

// ============ Phase A1: offset conv partials (4-way ci split) ===============
__global__ __launch_bounds__(256) void offset_kernel(
    const float* __restrict__ x, const float* __restrict__ w_off)
{
    __shared__ float  xs[18 * 18];
    __shared__ float4 ws4[81];                 // [27][12] padded weights
    float* ws = (float*)ws4;

    int b     = blockIdx.y;
    int chunk = blockIdx.z;                    // ci chunk of 64
    int tile  = blockIdx.x;                    // 16 tiles of 16x16
    int h0 = (tile >> 2) << 4;
    int w0 = (tile & 3) << 4;
    int tid = threadIdx.x;
    int ty = tid >> 4, tx = tid & 15;
    int h = h0 + ty, ww = w0 + tx;

    float acc[27];
#pragma unroll
    for (int i = 0; i < 27; i++) acc[i] = 0.f;

    const float* xb = x + b * (CI * HW);
    int ci0 = chunk << 6;
    for (int cit = 0; cit < 64; cit++) {
        int ci = ci0 + cit;
        __syncthreads();
        for (int i = tid; i < 324; i += 256) {
            int r = i / 18, c = i - r * 18;
            int gy = h0 + r - 1, gx = w0 + c - 1;
            float v = 0.f;
            if (gy >= 0 && gy < H && gx >= 0 && gx < W)
                v = xb[ci * HW + gy * W + gx];
            xs[i] = v;
        }
        for (int i = tid; i < 324; i += 256) {
            int oc = i / 12, j = i - oc * 12;
            ws[i] = (j < 9) ? w_off[oc * KDIM + ci * 9 + j] : 0.f;
        }
        __syncthreads();

        float xv[9];
#pragma unroll
        for (int ky = 0; ky < 3; ky++)
#pragma unroll
            for (int kx = 0; kx < 3; kx++)
                xv[ky * 3 + kx] = xs[(ty + ky) * 18 + tx + kx];

        const float4* w4 = (const float4*)ws;
#pragma unroll
        for (int oc = 0; oc < 27; oc++) {
            float4 a0 = w4[oc * 3 + 0], a1 = w4[oc * 3 + 1], a2 = w4[oc * 3 + 2];
            acc[oc] += xv[0] * a0.x + xv[1] * a0.y + xv[2] * a0.z + xv[3] * a0.w
                     + xv[4] * a1.x + xv[5] * a1.y + xv[6] * a1.z + xv[7] * a1.w
                     + xv[8] * a2.x;
        }
    }

    int m = b * HW + h * W + ww;
#pragma unroll
    for (int oc = 0; oc < 27; oc++)
        g_om[(chunk * 27 + oc) * M_TOT + m] = acc[oc];
}

// ============ Phase A2: reduce partials -> bilinear params ==================
__global__ __launch_bounds__(256) void reduce_kernel(const float* __restrict__ b_off)
{
    int m = blockIdx.x * 256 + threadIdx.x;
    int b = m >> 12, pix = m & 4095;
    int h = pix >> 6, ww = pix & 63;

    float om[27];
#pragma unroll
    for (int oc = 0; oc < 27; oc++) {
        float s = b_off[oc];
#pragma unroll
        for (int c = 0; c < 4; c++)
            s += g_om[(c * 27 + oc) * M_TOT + m];
        om[oc] = s;
    }
#pragma unroll
    for (int kk = 0; kk < 9; kk++) {
        float msk = 1.f / (1.f + __expf(-om[18 + kk]));
        float py = (float)(h  + (kk / 3) - 1) + om[kk];
        float px = (float)(ww + (kk % 3) - 1) + om[9 + kk];
        g_par[(b * 9 + kk) * HW + pix] = make_float4(py, px, msk, 0.f);
    }
}

// ======= Phase W: scaled weights, perm8-laid-out =============================
__global__ void wt_kernel(const float* __restrict__ w,
                          const float* __restrict__ gamma,
                          const float* __restrict__ var)
{
    int co = blockIdx.x;
    float alpha = gamma[co] * rsqrtf(var[co] + EPSV);
    for (int k = threadIdx.x; k < KDIM; k += 256) {
        int pos = (k & ~7) + ((k & 3) << 1) + ((k & 7) >> 2);
        g_wB[co * KDIM + pos] = tf32_rna(w[co * KDIM + k] * alpha);
    }
}

// ============ Phase B: bilinear sampling (NHWC) -> g_valA[m][k perm8] =======
// One warp per pixel (8 pixels / 256-thread block). Lane <-> ci quad:
// every corner read is a 512B fully-coalesced float4 load from g_xT.
__global__ __launch_bounds__(256) void sample_kernel()
{
    __shared__ float sbuf[8 * 9 * 132];       // [pix][kk][128ci + 4 pad] = 38016 B
    int tid  = threadIdx.x;
    int warp = tid >> 5, lane = tid & 31;
    int m0 = blockIdx.x << 3;                 // 8 pixels per block
    int m  = m0 + warp;
    int b = m >> 12, pix = m & 4095;

    int    base[9];
    float4 wq[9];                             // (w00, w01, w10, w11) fused with mask
#pragma unroll
    for (int kk = 0; kk < 9; kk++) {
        float4 par = g_par[(b * 9 + kk) * HW + pix];   // warp-uniform broadcast
        float py = par.x, px = par.y, msk = par.z;
        float y0f = floorf(py), x0f = floorf(px);
        float wy = py - y0f, wx = px - x0f;
        int y0 = (int)y0f, x0 = (int)x0f;

        int yT = min(max(y0, 0), H - 2);
        int xL = min(max(x0, 0), W - 2);
        float wyt = (yT == y0) ? (1.f - wy) : ((yT == y0 + 1) ? wy : 0.f);
        float wyb = (yT + 1 == y0) ? (1.f - wy) : ((yT == y0) ? wy : 0.f);
        float wxl = (xL == x0) ? (1.f - wx) : ((xL == x0 + 1) ? wx : 0.f);
        float wxr = (xL + 1 == x0) ? (1.f - wx) : ((xL == x0) ? wx : 0.f);
        wyt *= msk; wyb *= msk;

        base[kk] = yT * W + xL;
        wq[kk] = make_float4(wyt * wxl, wyt * wxr, wyb * wxl, wyb * wxr);
    }

    const float* xTb = g_xT + (size_t)b * HW * CI;
    float4* sb4 = (float4*)sbuf;

    for (int half = 0; half < 2; half++) {
        int ci0 = (half << 7) + (lane << 2);
#pragma unroll
        for (int kk = 0; kk < 9; kk++) {
            const float* p00 = xTb + (size_t)base[kk] * CI + ci0;
            float4 a  = *(const float4*)(p00);
            float4 bq = *(const float4*)(p00 + CI);
            float4 c  = *(const float4*)(p00 + W * CI);
            float4 d  = *(const float4*)(p00 + (W + 1) * CI);
            float4 wv = wq[kk];
            float4 v;
            v.x = tf32_rna(wv.x * a.x + wv.y * bq.x + wv.z * c.x + wv.w * d.x);
            v.y = tf32_rna(wv.x * a.y + wv.y * bq.y + wv.z * c.y + wv.w * d.y);
            v.z = tf32_rna(wv.x * a.z + wv.y * bq.z + wv.z * c.z + wv.w * d.z);
            v.w = tf32_rna(wv.x * a.w + wv.y * bq.w + wv.z * c.w + wv.w * d.w);
            sb4[(warp * 9 + kk) * 33 + lane] = v;      // STS.128, conflict-free
        }
        __syncthreads();
        // write half (1152 k per pixel) to gmem in perm8 layout, coalesced
#pragma unroll
        for (int t = 0; t < 9; t++) {
            int i  = tid + (t << 8);          // 0..2303 (float4 units this half)
            int pw = i / 288;
            int p0 = (i - pw * 288) << 2;     // local perm position
            float4 v;
#pragma unroll
            for (int j = 0; j < 4; j++) {
                int kl  = p8inv(p0 + j);
                int cil = kl / 9;
                int kk  = kl - cil * 9;
                ((float*)&v)[j] = sbuf[(pw * 9 + kk) * 132 + cil];
            }
            *(float4*)&g_valA[(size_t)(m0 + pw) * KDIM + half * 1152 + p0] = v;
        }
        __syncthreads();
    }
}

// ============ Phase C: mma.sync tf32 GEMM + bias/BN-shift/ReLU ==============
// Block: M=128, N=256, KC=32; 512 threads = 16 warps as 4(m) x 4(n);
// warp tile m32 x n64 -> acc[2][8][4]. 3-stage cp.async pipeline, A and B.
#define KC     32
#define NSTG   72                 // 2304/32
#define SSTR   36                 // smem row stride (floats)
#define ASZ    (128 * SSTR)
#define BSZ    (256 * SSTR)
#define NBUF   3
#define DSMEM  ((ASZ + BSZ) * NBUF * 4)

__global__ __launch_bounds__(512, 1) void gemm_kernel(
    const float* __restrict__ bias,  const float* __restrict__ gamma,
    const float* __restrict__ beta,  const float* __restrict__ mean,
    const float* __restrict__ var,   float* __restrict__ out)
{
    extern __shared__ float dynf[];
    __shared__ float s_delta[CO];

    int tid  = threadIdx.x;
    int wid  = tid >> 5, lane = tid & 31;
    int gid  = lane >> 2, q = lane & 3;
    int wm   = wid & 3, wn = wid >> 2;

    float* As[NBUF];
    float* Bs[NBUF];
#pragma unroll
    for (int i = 0; i < NBUF; i++) {
        As[i] = dynf + i * (ASZ + BSZ);
        Bs[i] = As[i] + ASZ;
    }

    if (tid < 256) {
        float alpha = gamma[tid] * rsqrtf(var[tid] + EPSV);
        s_delta[tid] = fmaf(bias[tid] - mean[tid], alpha, beta[tid]);
    }

    int m0 = blockIdx.x << 7;

    float acc[2][8][4];
#pragma unroll
    for (int ma = 0; ma < 2; ma++)
#pragma unroll
        for (int na = 0; na < 8; na++)
#pragma unroll
            for (int e = 0; e < 4; e++) acc[ma][na][e] = 0.f;

#define FILL(sidx, buf) do {                                                   \
    const int k0 = (sidx) * KC;                                                \
    _Pragma("unroll")                                                          \
    for (int t = 0; t < 2; t++) {                                              \
        int idx4 = tid + (t << 9);                                             \
        int r = idx4 >> 3, c = idx4 & 7;                                       \
        cp_async16(smem_u32(&As[buf][r * SSTR + (c << 2)]),                    \
                   &g_valA[(size_t)(m0 + r) * KDIM + k0 + (c << 2)]);          \
    }                                                                          \
    _Pragma("unroll")                                                          \
    for (int t = 0; t < 4; t++) {                                              \
        int idx4 = tid + (t << 9);                                             \
        int r = idx4 >> 3, c = idx4 & 7;                                       \
        cp_async16(smem_u32(&Bs[buf][r * SSTR + (c << 2)]),                    \
                   &g_wB[r * KDIM + k0 + (c << 2)]);                           \
    }                                                                          \
} while (0)

    FILL(0, 0); CP_COMMIT();
    FILL(1, 1); CP_COMMIT();

    for (int s = 0; s < NSTG; s++) {
        int buf = s % NBUF;
        if (s + 2 < NSTG) {
            int nb = (s + 2) % NBUF;
            FILL(s + 2, nb);
        }
        CP_COMMIT();               // uniform group count (may be empty at tail)
        CP_WAIT2();                // oldest group (stage s) complete
        __syncthreads();

        const float* Ab = As[buf];
        const float* Bb = Bs[buf];
#pragma unroll
        for (int j = 0; j < 4; j++) {
            uint32_t af[2][4];
#pragma unroll
            for (int ma = 0; ma < 2; ma++) {
                int r0 = wm * 32 + ma * 16 + gid;
                float2 v0 = *(const float2*)&Ab[r0 * SSTR + j * 8 + q * 2];
                float2 v1 = *(const float2*)&Ab[(r0 + 8) * SSTR + j * 8 + q * 2];
                af[ma][0] = __float_as_uint(v0.x);
                af[ma][1] = __float_as_uint(v1.x);
                af[ma][2] = __float_as_uint(v0.y);
                af[ma][3] = __float_as_uint(v1.y);
            }
#pragma unroll
            for (int na = 0; na < 8; na++) {
                int n = wn * 64 + na * 8 + gid;
                float2 bv = *(const float2*)&Bb[n * SSTR + j * 8 + q * 2];
                uint32_t b0 = __float_as_uint(bv.x);
                uint32_t b1 = __float_as_uint(bv.y);
#pragma unroll
                for (int ma = 0; ma < 2; ma++)
                    mma_tf32(acc[ma][na][0], acc[ma][na][1], acc[ma][na][2], acc[ma][na][3],
                             af[ma][0], af[ma][1], af[ma][2], af[ma][3], b0, b1);
            }
        }
        __syncthreads();           // buffer reuse safety for next FILL
    }

    // ---- epilogue ----
    int b   = m0 >> 12;
    int hw0 = m0 & 4095;
    float* ob = out + b * (CO * HW);
#pragma unroll
    for (int ma = 0; ma < 2; ma++) {
#pragma unroll
        for (int na = 0; na < 8; na++) {
#pragma unroll
            for (int e = 0; e < 4; e++) {
                int row = wm * 32 + ma * 16 + gid + ((e >> 1) << 3);
                int co  = wn * 64 + na * 8 + (q << 1) + (e & 1);
                float v = acc[ma][na][e] + s_delta[co];
                ob[co * HW + hw0 + row] = fmaxf(v, 0.f);
            }
        }
    }
}

// ===========================================================================
extern "C" void kernel_launch(void* const* d_in, const int* in_sizes, int n_in,
                              void* d_out, int out_size)
{
    const float* x     = (const float*)d_in[0];
    const float* w_off = (const float*)d_in[1];
    const float* b_off = (const float*)d_in[2];
    const float* w     = (const float*)d_in[3];
    const float* bias  = (const float*)d_in[4];
    const float* gamma = (const float*)d_in[5];
    const float* beta  = (const float*)d_in[6];
    const float* mean  = (const float*)d_in[7];
    const float* var   = (const float*)d_in[8];
    float* out = (float*)d_out;

    cudaFuncSetAttribute(gemm_kernel, cudaFuncAttributeMaxDynamicSharedMemorySize, DSMEM);

    transpose_kernel<<<dim3(128, 8, 8), 256>>>(x);
    offset_kernel<<<dim3(16, 8, 4), 256>>>(x, w_off);
    reduce_kernel<<<M_TOT / 256, 256>>>(b_off);
    wt_kernel<<<CO, 256>>>(w, gamma, var);
    sample_kernel<<<M_TOT / 8, 256>>>();
    gemm_kernel<<<M_TOT / 128, 512, DSMEM>>>(bias, gamma, beta, mean, var, out);
}